// round 17
// baseline (speedup 1.0000x reference)
#include <cuda_runtime.h>
#include <cuda_fp16.h>
#include <cstdint>

// D[b,o] = sum_ck A[b,ck] * W[o,ck] — GEMM M=256, N=1024, K=16384, fp32 I/O.
// fp16 operands (converted at STS), fp32 accumulate, mma.sync m16n8k16.
// R15: combine R14's proven 32x64 warp tiles (low LDSM/MAC) with 128x128 CTA
// tile (balanced LDG) at 256 threads / 8 warps and TWO CTAs per SM
// (launch_bounds(256,2)) — independent barrier sets cover each other's
// stalls (the measured ~500cyc/iter latency exposure). Order preserved:
// LDG -> MMA(ks0,ks1) -> STS -> BAR. SPLITK=16 -> (8,2,16)=256 CTAs, one
// wave at 2 CTAs/SM. Zero-init + atomicAdd split-K epilogue (R13-proven).
#define B_DIM   256
#define N_DIM   1024
#define K_DIM   16384
#define TILE_M  128
#define TILE_N  128
#define TILE_K  32
#define SPLITK  16
#define K_PER_CTA (K_DIM / SPLITK)       // 1024
#define NITER   (K_PER_CTA / TILE_K)     // 32
#define NTHREADS 256

// Smem rows: 32 halfs (64 B) padded to stride 80 B -> conflict-free ldmatrix.
#define ROW_HB   80
#define A_HB     (128 * ROW_HB)           // 10240 B
#define STAGE_HB (2 * A_HB)               // A + B = 20480 B
#define SMEM_BYTES (2 * STAGE_HB)         // 40960 B (static; 2 CTAs = 80KB/SM)

__device__ __forceinline__ uint32_t smem_u32(const void* p) {
    uint32_t a;
    asm("{ .reg .u64 t; cvta.to.shared.u64 t, %1; cvt.u32.u64 %0, t; }" : "=r"(a) : "l"(p));
    return a;
}

__device__ __forceinline__ void ldmx4(uint32_t* r, uint32_t addr) {
    asm volatile("ldmatrix.sync.aligned.m8n8.x4.shared.b16 {%0,%1,%2,%3}, [%4];"
                 : "=r"(r[0]), "=r"(r[1]), "=r"(r[2]), "=r"(r[3]) : "r"(addr));
}

__device__ __forceinline__ void mma16816(float* d, const uint32_t* a, const uint32_t* b) {
    asm volatile(
        "mma.sync.aligned.m16n8k16.row.col.f32.f16.f16.f32 "
        "{%0,%1,%2,%3}, {%4,%5,%6,%7}, {%8,%9}, {%0,%1,%2,%3};"
        : "+f"(d[0]), "+f"(d[1]), "+f"(d[2]), "+f"(d[3])
        : "r"(a[0]), "r"(a[1]), "r"(a[2]), "r"(a[3]), "r"(b[0]), "r"(b[1]));
}

__device__ __forceinline__ uint2 pack4h(float4 v) {
    __half2 lo = __floats2half2_rn(v.x, v.y);
    __half2 hi = __floats2half2_rn(v.z, v.w);
    uint2 r;
    r.x = *(uint32_t*)&lo;
    r.y = *(uint32_t*)&hi;
    return r;
}

__global__ void StreamingConv_zero_kernel(float* __restrict__ out)
{
    const int idx = blockIdx.x * blockDim.x + threadIdx.x;   // float4 index
    ((float4*)out)[idx] = make_float4(0.f, 0.f, 0.f, 0.f);
}

__global__ void __launch_bounds__(NTHREADS, 2)
StreamingConv_gemm_kernel(const float* __restrict__ A, const float* __restrict__ W,
                          float* __restrict__ out)
{
    __shared__ __align__(16) char smem[SMEM_BYTES];
    const uint32_t sb = smem_u32(smem);

    const int tid = threadIdx.x;
    const int lane = tid & 31;
    const int wid = tid >> 5;
    const int wm = wid >> 1;          // 0..3 -> 32-row band of M
    const int wn = wid & 1;           // 0..1 -> 64-col band of N

    const int m0 = blockIdx.y * TILE_M;
    const int n0 = blockIdx.x * TILE_N;
    const int sk = blockIdx.z;
    const size_t kbase = (size_t)sk * K_PER_CTA;

    // ---- gmem load mapping: A and B tiles each 128 rows x 8 float4 ----
    // 1024 float4 / 256 threads = 4 per thread per tile.
    const float* pa[4];
    const float* pb[4];
    uint32_t s_off[4];
    #pragma unroll
    for (int i = 0; i < 4; i++) {
        const int idx = tid + NTHREADS * i;
        const int row = idx >> 3;     // 0..127
        const int c4  = idx & 7;
        pa[i] = A + (size_t)(m0 + row) * K_DIM + kbase + c4 * 4;
        pb[i] = W + (size_t)(n0 + row) * K_DIM + kbase + c4 * 4;
        s_off[i] = (uint32_t)(row * ROW_HB + c4 * 8);
    }

    // ---- ldmatrix per-lane tile offsets (add ks*32 at use) ----
    uint32_t a_off[2];
    #pragma unroll
    for (int mt = 0; mt < 2; mt++)
        a_off[mt] = (uint32_t)((wm * 32 + mt * 16 + (lane & 15)) * ROW_HB + (lane >> 4) * 16);
    uint32_t b_off[4];
    #pragma unroll
    for (int pj = 0; pj < 4; pj++)
        b_off[pj] = (uint32_t)(A_HB + (wn * 64 + (2 * pj + (lane >> 4)) * 8 + (lane & 7)) * ROW_HB
                               + ((lane >> 3) & 1) * 16);

    float acc[2][8][4];
    #pragma unroll
    for (int mt = 0; mt < 2; mt++)
        #pragma unroll
        for (int nt = 0; nt < 8; nt++)
            #pragma unroll
            for (int j = 0; j < 4; j++) acc[mt][nt][j] = 0.f;

    // ---- prologue: chunk 0 -> stage 0 ----
    #pragma unroll
    for (int i = 0; i < 4; i++) {
        *(uint2*)(smem + s_off[i])        = pack4h(*(const float4*)pa[i]);
        *(uint2*)(smem + A_HB + s_off[i]) = pack4h(*(const float4*)pb[i]);
    }
    __syncthreads();

    #pragma unroll 2
    for (int it = 0; it < NITER; ++it) {
        // 1-deep queue: LDG chunk it+1 (raw fp32; cvt at STS after the MMAs)
        float4 qa[4], qb[4];
        if (it + 1 < NITER) {
            const size_t ko = (size_t)(it + 1) * TILE_K;
            #pragma unroll
            for (int i = 0; i < 4; i++) qa[i] = *(const float4*)(pa[i] + ko);
            #pragma unroll
            for (int i = 0; i < 4; i++) qb[i] = *(const float4*)(pb[i] + ko);
        }

        // compute current tile from stage it&1 (two k16 steps)
        const uint32_t base = sb + (uint32_t)(it & 1) * STAGE_HB;
        #pragma unroll
        for (int ks = 0; ks < 2; ks++) {
            uint32_t afr[2][4], bfr[4][4];
            #pragma unroll
            for (int mt = 0; mt < 2; mt++) ldmx4(afr[mt], base + a_off[mt] + ks * 32);
            #pragma unroll
            for (int pj = 0; pj < 4; pj++) ldmx4(bfr[pj], base + b_off[pj] + ks * 32);
            #pragma unroll
            for (int mt = 0; mt < 2; mt++)
                #pragma unroll
                for (int nt = 0; nt < 8; nt++) {
                    uint32_t bb[2] = { bfr[nt >> 1][(nt & 1) * 2], bfr[nt >> 1][(nt & 1) * 2 + 1] };
                    mma16816(acc[mt][nt], afr[mt], bb);
                }
        }

        // convert + store chunk it+1 into the other stage
        if (it + 1 < NITER) {
            const uint32_t nxt = (uint32_t)((it + 1) & 1) * STAGE_HB;
            #pragma unroll
            for (int i = 0; i < 4; i++) {
                *(uint2*)(smem + nxt + s_off[i])        = pack4h(qa[i]);
                *(uint2*)(smem + nxt + A_HB + s_off[i]) = pack4h(qb[i]);
            }
        }
        __syncthreads();
    }

    // ---- epilogue: atomically accumulate this split's tile into out ----
    #pragma unroll
    for (int mt = 0; mt < 2; mt++) {
        const int row0 = m0 + wm * 32 + mt * 16 + (lane >> 2);
        #pragma unroll
        for (int nt = 0; nt < 8; nt++) {
            const int col = n0 + wn * 64 + nt * 8 + 2 * (lane & 3);
            atomicAdd(&out[(size_t)row0 * N_DIM + col],           acc[mt][nt][0]);
            atomicAdd(&out[(size_t)row0 * N_DIM + col + 1],       acc[mt][nt][1]);
            atomicAdd(&out[(size_t)(row0 + 8) * N_DIM + col],     acc[mt][nt][2]);
            atomicAdd(&out[(size_t)(row0 + 8) * N_DIM + col + 1], acc[mt][nt][3]);
        }
    }
}

extern "C" void kernel_launch(void* const* d_in, const int* in_sizes, int n_in,
                              void* d_out, int out_size)
{
    const float* A = (const float*)d_in[0];   // curr_input [256, 1024, 16]
    const float* W = (const float*)d_in[1];   // weight     [1024, 1024, 16]
    float* out = (float*)d_out;               // [256, 1024]

    StreamingConv_zero_kernel<<<(B_DIM * N_DIM / 4) / 256, 256>>>(out);

    dim3 grid(N_DIM / TILE_N, B_DIM / TILE_M, SPLITK);   // (8, 2, 16) = 256 CTAs
    StreamingConv_gemm_kernel<<<grid, NTHREADS>>>(A, W, out);
}